// round 1
// baseline (speedup 1.0000x reference)
#include <cuda_runtime.h>

#define CIN   256
#define COUT  256
#define LEN   8192
#define KK    7
#define BATCH 4
#define TL    128    // l-tile of main kernel
#define TLO   128    // l-tile of offsets kernel

typedef unsigned long long ull;

// ---------- device scratch (no allocations allowed) ----------
__device__ float  g_wt[KK * CIN * COUT];      // [k][i][o]  transposed weight
__device__ int2   g_tidx[BATCH * KK * LEN];   // (x0c, x1c)
__device__ float2 g_tw[BATCH * KK * LEN];     // (wa, wb)

// ---------- f32x2 helpers ----------
__device__ __forceinline__ ull pack2(float lo, float hi) {
    ull r; asm("mov.b64 %0, {%1, %2};" : "=l"(r) : "f"(lo), "f"(hi)); return r;
}
__device__ __forceinline__ void unpack2(ull v, float& lo, float& hi) {
    asm("mov.b64 {%0, %1}, %2;" : "=f"(lo), "=f"(hi) : "l"(v));
}
#define FMA2(d, a, b) asm("fma.rn.f32x2 %0, %1, %2, %0;" : "+l"(d) : "l"(a), "l"(b))

// ---------- kernel 1: weight transpose (Cout,Cin,K) -> [k][i][o] ----------
__global__ void wt_kernel(const float* __restrict__ w) {
    int e = blockIdx.x * 256 + threadIdx.x;
    if (e < KK * CIN * COUT) {
        int o = e & 255;
        int r = e >> 8;
        int i = r & 255;
        int k = r >> 8;
        g_wt[e] = w[(o * CIN + i) * KK + k];
    }
}

// ---------- kernel 2: offset conv + interpolation tables ----------
// block = (l-tile of 128, b). smem: x slab [256][136] + offset_w [7][256][8]
__global__ __launch_bounds__(256, 1) void offsets_kernel(
    const float* __restrict__ x,
    const float* __restrict__ ow,
    const float* __restrict__ ob)
{
    extern __shared__ float sm[];
    float* xs  = sm;              // 256 * 136 floats
    float* ows = sm + 256 * 136;  // 7 * 256 * 8 floats

    int tid = threadIdx.x;
    int b   = blockIdx.y;
    int l0  = blockIdx.x * TLO;
    const float* xb = x + (size_t)b * CIN * LEN;

    // load x slab (logical cols 0..133 map to global l0-3 .. l0+130), zero-pad OOB
    for (int idx = tid; idx < 256 * 134; idx += 256) {
        int i = idx / 134;
        int c = idx - i * 134;
        int g = l0 - 3 + c;
        xs[i * 136 + c] = (g >= 0 && g < LEN) ? xb[i * LEN + g] : 0.0f;
    }
    // load offset weights, pad inner dim 7->8
    for (int e = tid; e < KK * CIN * KK; e += 256) {
        int r  = e / 7;
        int kk = e - r * 7;
        ows[r * 8 + kk] = ow[e];
    }
    __syncthreads();

    int w    = tid >> 5;
    int lane = tid & 31;
    if (w < 7) {
        int k = w;
        float a0 = 0.f, a1 = 0.f, a2 = 0.f, a3 = 0.f;   // 4 consecutive l per lane
        const float* xrow0 = xs + 4 * lane;
        const float* wrow  = ows + k * 256 * 8;
        #pragma unroll 4
        for (int i = 0; i < 256; i++) {
            const float4* xr = (const float4*)(xrow0 + i * 136);
            float4 A = xr[0], B4 = xr[1], C4 = xr[2];
            float xw[12] = {A.x, A.y, A.z, A.w, B4.x, B4.y, B4.z, B4.w,
                            C4.x, C4.y, C4.z, C4.w};
            const float4* wr = (const float4*)(wrow + i * 8);
            float4 W0 = wr[0], W1 = wr[1];
            float wv[7] = {W0.x, W0.y, W0.z, W0.w, W1.x, W1.y, W1.z};
            #pragma unroll
            for (int kk = 0; kk < 7; kk++) {
                a0 += wv[kk] * xw[0 + kk];
                a1 += wv[kk] * xw[1 + kk];
                a2 += wv[kk] * xw[2 + kk];
                a3 += wv[kk] * xw[3 + kk];
            }
        }
        float bk = ob[k];
        float accs[4] = {a0, a1, a2, a3};
        #pragma unroll
        for (int d = 0; d < 4; d++) {
            int l  = 4 * lane + d;
            int lg = l0 + l;
            // loc = l + k + offset  (p + p_k + PAD collapses to l + k)
            float loc = (float)(lg + k) + accs[d] + bk;
            float fl  = floorf(loc);
            int ix0 = (int)fl;
            int ix1 = ix0 + 1;
            int i0c = min(max(ix0, 0), LEN - 1);
            int i1c = min(max(ix1, 0), LEN - 1);
            float wa = (float)i1c - loc;
            float wb = loc - (float)i0c;
            int o = (b * 7 + k) * LEN + lg;
            g_tidx[o] = make_int2(i0c, i1c);
            g_tw[o]   = make_float2(wa, wb);
        }
    }
}

// ---------- kernel 3: main fused interp + GEMM (f32x2) ----------
// block = (b, l-tile of 128), computes all 256 Cout for 128 l positions.
// thread tile: 8 o x 16 l held as 64 f32x2 accumulators.
__global__ __launch_bounds__(256, 1) void main_kernel(
    const float* __restrict__ x,
    const float* __restrict__ bias,
    float* __restrict__ out)
{
    extern __shared__ float sm[];
    float* interp_s = sm;                         // 256 x 128 floats (128 KB)
    ull*   w_dup    = (ull*)(sm + 256 * 128);     // 32 x 256 ull, duplicated (64 KB)
    int2*   s_idx   = (int2*)(sm + 256 * 128 + 32 * 256 * 2);
    float2* s_w     = (float2*)(s_idx + TL);

    int tid = threadIdx.x;
    int b   = blockIdx.y;
    int l0  = blockIdx.x * TL;
    int og  = tid >> 3;    // 0..31 -> o rows og*8 .. og*8+7
    int lg  = tid & 7;     // 0..7  -> l cols lg*16 .. lg*16+15
    const float* xb = x + (size_t)b * CIN * LEN;

    ull acc[8][8];
    #pragma unroll
    for (int j = 0; j < 8; j++)
        #pragma unroll
        for (int m = 0; m < 8; m++) acc[j][m] = 0ull;

    for (int k = 0; k < KK; k++) {
        // load interpolation tables for this (b,k,l-tile)
        if (tid < TL) {
            int o = (b * 7 + k) * LEN + l0 + tid;
            s_idx[tid] = g_tidx[o];
            s_w[tid]   = g_tw[o];
        }
        __syncthreads();

        // build interp tile: interp_s[i][l] = wa*x[i,x0] + wb*x[i,x1]
        {
            int l  = tid & 127;
            int i0 = tid >> 7;       // 0 or 1
            int2   ii = s_idx[l];
            float2 wv = s_w[l];
            const float* p0 = xb + ii.x;
            const float* p1 = xb + ii.y;
            #pragma unroll 8
            for (int i = i0; i < 256; i += 2) {
                interp_s[i * 128 + l] = wv.x * p0[i * LEN] + wv.y * p1[i * LEN];
            }
        }
        __syncthreads();

        const float* wt_k = g_wt + k * CIN * COUT;
        for (int ic = 0; ic < 8; ic++) {     // 8 chunks of 32 i
            // fill duplicated weight tile: w_dup[i][o] = (w,w)
            const float4* src = (const float4*)(wt_k + ic * 32 * COUT);
            for (int e = tid; e < 2048; e += 256) {
                float4 v = src[e];
                ull* dst = w_dup + e * 4;
                dst[0] = pack2(v.x, v.x);
                dst[1] = pack2(v.y, v.y);
                dst[2] = pack2(v.z, v.z);
                dst[3] = pack2(v.w, v.w);
            }
            __syncthreads();

            const float* isp = interp_s + (ic * 32) * 128 + lg * 16;
            const ull*   wd  = w_dup + og * 8;
            #pragma unroll 4
            for (int i = 0; i < 32; i++) {
                const ulonglong2* ap = (const ulonglong2*)(wd + i * 256);
                ulonglong2 a0 = ap[0], a1 = ap[1], a2 = ap[2], a3 = ap[3];
                const ulonglong2* bp = (const ulonglong2*)(isp + i * 128);
                ulonglong2 b0 = bp[0], b1 = bp[1], b2 = bp[2], b3 = bp[3];
                ull A[8]  = {a0.x, a0.y, a1.x, a1.y, a2.x, a2.y, a3.x, a3.y};
                ull Bv[8] = {b0.x, b0.y, b1.x, b1.y, b2.x, b2.y, b3.x, b3.y};
                #pragma unroll
                for (int j = 0; j < 8; j++)
                    #pragma unroll
                    for (int m = 0; m < 8; m++)
                        FMA2(acc[j][m], A[j], Bv[m]);
            }
            __syncthreads();
        }
    }

    // epilogue: add bias, store
    #pragma unroll
    for (int j = 0; j < 8; j++) {
        int o = og * 8 + j;
        float bj = bias[o];
        float* orow = out + ((size_t)(b * COUT + o)) * LEN + l0 + lg * 16;
        #pragma unroll
        for (int m = 0; m < 8; m++) {
            float lo, hi;
            unpack2(acc[j][m], lo, hi);
            ((float2*)orow)[m] = make_float2(lo + bj, hi + bj);
        }
    }
}

// ---------- launch ----------
extern "C" void kernel_launch(void* const* d_in, const int* in_sizes, int n_in,
                              void* d_out, int out_size)
{
    const float* x        = (const float*)d_in[0];
    const float* weight   = (const float*)d_in[1];
    const float* bias     = (const float*)d_in[2];
    const float* offset_w = (const float*)d_in[3];
    const float* offset_b = (const float*)d_in[4];
    float* out = (float*)d_out;

    const int smem_off  = (256 * 136 + 7 * 256 * 8) * 4;            // 196608
    const int smem_main = 256 * 128 * 4 + 32 * 256 * 8
                        + TL * 8 + TL * 8;                          // 198656

    cudaFuncSetAttribute(offsets_kernel, cudaFuncAttributeMaxDynamicSharedMemorySize, smem_off);
    cudaFuncSetAttribute(main_kernel,    cudaFuncAttributeMaxDynamicSharedMemorySize, smem_main);

    wt_kernel<<<(KK * CIN * COUT + 255) / 256, 256>>>(weight);
    offsets_kernel<<<dim3(LEN / TLO, BATCH), 256, smem_off>>>(x, offset_w, offset_b);
    main_kernel<<<dim3(LEN / TL, BATCH), 256, smem_main>>>(x, bias, out);
}